// round 5
// baseline (speedup 1.0000x reference)
#include <cuda_runtime.h>
#include <cuda_bf16.h>
#include <cstdint>

// Problem sizes
#define NROWS 8192
#define INF   2048
#define OUTF  2048

// Scratch (device globals — no allocation allowed)
__device__ __nv_bfloat16 g_Aq[(size_t)NROWS * INF];   // sign(input)/gamma, bf16 (32 MB)
__device__ __nv_bfloat16 g_Wq[(size_t)OUTF * INF];    // sign(weight), bf16 (8 MB)
__device__ float         g_scale[NROWS];              // per-row max-abs

// ---------------------------------------------------------------------------
// Helpers
// ---------------------------------------------------------------------------
__device__ __forceinline__ uint32_t smem_u32(const void* p) {
    uint32_t a;
    asm("{ .reg .u64 t; cvta.to.shared.u64 t, %1; cvt.u32.u64 %0, t; }"
        : "=r"(a) : "l"(p));
    return a;
}

__device__ __forceinline__ void cp_async16(uint32_t dst, const void* src) {
    asm volatile("cp.async.cg.shared.global [%0], [%1], 16;"
                 :: "r"(dst), "l"(src) : "memory");
}
#define CP_COMMIT()  asm volatile("cp.async.commit_group;" ::: "memory")
#define CP_WAIT2()   asm volatile("cp.async.wait_group 2;" ::: "memory")

__device__ __forceinline__ void ldsm_x4(uint32_t* r, uint32_t addr) {
    asm volatile("ldmatrix.sync.aligned.m8n8.x4.shared.b16 {%0,%1,%2,%3}, [%4];"
                 : "=r"(r[0]), "=r"(r[1]), "=r"(r[2]), "=r"(r[3]) : "r"(addr));
}

__device__ __forceinline__ void mma16816(float* c, const uint32_t* a, const uint32_t* b) {
    asm volatile(
        "mma.sync.aligned.m16n8k16.row.col.f32.bf16.bf16.f32 "
        "{%0,%1,%2,%3}, {%4,%5,%6,%7}, {%8,%9}, {%0,%1,%2,%3};"
        : "+f"(c[0]), "+f"(c[1]), "+f"(c[2]), "+f"(c[3])
        : "r"(a[0]), "r"(a[1]), "r"(a[2]), "r"(a[3]), "r"(b[0]), "r"(b[1]));
}

// ---------------------------------------------------------------------------
// Kernel 1: per-row max-abs + sign-quantize input to bf16 (value = ±1/gamma)
// one block per row, 256 threads, 2048 floats/row
// ---------------------------------------------------------------------------
__device__ __forceinline__ unsigned short sgn_bf16(float x, float g) {
    float inv = 1.0f / g;
    float v = (x > 0.f) ? inv : ((x < 0.f) ? -inv : 0.f);
    return __bfloat16_as_ushort(__float2bfloat16_rn(v));
}

__global__ void __launch_bounds__(256)
quant_input_kernel(const float* __restrict__ in, const float* __restrict__ gamma) {
    int row = blockIdx.x;
    int t = threadIdx.x;
    const float4* rin = (const float4*)(in + (size_t)row * INF);
    float4 v0 = rin[t];
    float4 v1 = rin[t + 256];

    float m = fmaxf(fmaxf(fabsf(v0.x), fabsf(v0.y)), fmaxf(fabsf(v0.z), fabsf(v0.w)));
    m = fmaxf(m, fmaxf(fmaxf(fabsf(v1.x), fabsf(v1.y)), fmaxf(fabsf(v1.z), fabsf(v1.w))));
#pragma unroll
    for (int o = 16; o; o >>= 1) m = fmaxf(m, __shfl_xor_sync(0xffffffffu, m, o));

    __shared__ float red[8];
    if ((t & 31) == 0) red[t >> 5] = m;
    __syncthreads();
    if (t == 0) {
        float r = red[0];
#pragma unroll
        for (int i = 1; i < 8; i++) r = fmaxf(r, red[i]);
        g_scale[row] = r;
    }

    const float4* g4 = (const float4*)gamma;
    float4 ga = g4[t], gb = g4[t + 256];
    uint2 pa, pb;
    pa.x = (uint32_t)sgn_bf16(v0.x, ga.x) | ((uint32_t)sgn_bf16(v0.y, ga.y) << 16);
    pa.y = (uint32_t)sgn_bf16(v0.z, ga.z) | ((uint32_t)sgn_bf16(v0.w, ga.w) << 16);
    pb.x = (uint32_t)sgn_bf16(v1.x, gb.x) | ((uint32_t)sgn_bf16(v1.y, gb.y) << 16);
    pb.y = (uint32_t)sgn_bf16(v1.z, gb.z) | ((uint32_t)sgn_bf16(v1.w, gb.w) << 16);

    uint2* arow = (uint2*)(g_Aq + (size_t)row * INF);
    arow[t] = pa;
    arow[t + 256] = pb;
}

// ---------------------------------------------------------------------------
// Kernel 2: sign-quantize weight to bf16 (±1 exactly: 0x3F80 / 0xBF80)
// ---------------------------------------------------------------------------
__device__ __forceinline__ uint32_t sgnbits(float x) {
    return x > 0.f ? 0x3F80u : (x < 0.f ? 0xBF80u : 0u);
}

__global__ void __launch_bounds__(256)
quant_weight_kernel(const float* __restrict__ w) {
    size_t i = (size_t)blockIdx.x * 256 + threadIdx.x;  // float4 index
    float4 v = ((const float4*)w)[i];
    uint2 p;
    p.x = sgnbits(v.x) | (sgnbits(v.y) << 16);
    p.y = sgnbits(v.z) | (sgnbits(v.w) << 16);
    ((uint2*)g_Wq)[i] = p;
}

// ---------------------------------------------------------------------------
// Kernel 3: mma.sync bf16 GEMM. BM=256, BN=128, BK=64.
// 256 threads = 8 warps in 4(M) x 2(N) grid, warp tile 64x64.
// 4-stage cp.async pipeline, SW128-swizzled SMEM (128 B rows).
// Epilogue: out = (acc * scale_row + bias) * beta.
// ---------------------------------------------------------------------------
static constexpr int BM = 256, BN = 128, BK = 64;
static constexpr int A_BYTES   = BM * 128;              // 32 KB (BK*2 = 128 B rows)
static constexpr int B_BYTES   = BN * 128;              // 16 KB
static constexpr int STAGE     = A_BYTES + B_BYTES;     // 48 KB
static constexpr int NSTAGES   = 4;
static constexpr int SMEM_TOTAL = NSTAGES * STAGE;      // 192 KB
static constexpr int NT = INF / BK;                     // 32 k-tiles

// swizzled byte offset within a tile: row has 8 chunks of 16 B
__device__ __forceinline__ int sw_off(int row, int chunk) {
    return row * 128 + ((chunk ^ (row & 7)) << 4);
}

__device__ __forceinline__ void load_stage(char* smem, int stage,
                                           const __nv_bfloat16* Ag,
                                           const __nv_bfloat16* Bg,
                                           int kt, int tid) {
    uint32_t base = smem_u32(smem + stage * STAGE);
    // A: 256 rows x 8 chunks = 2048 chunks, 8 per thread
#pragma unroll
    for (int j = 0; j < 8; j++) {
        int e = j * 256 + tid;
        int r = e >> 3, c = e & 7;
        const char* src = (const char*)(Ag + (size_t)r * INF + kt * BK) + c * 16;
        cp_async16(base + sw_off(r, c), src);
    }
    // B: 128 rows x 8 chunks = 1024 chunks, 4 per thread
#pragma unroll
    for (int j = 0; j < 4; j++) {
        int e = j * 256 + tid;
        int r = e >> 3, c = e & 7;
        const char* src = (const char*)(Bg + (size_t)r * INF + kt * BK) + c * 16;
        cp_async16(base + A_BYTES + sw_off(r, c), src);
    }
}

__global__ void __launch_bounds__(256, 1)
bitlinear_gemm(const float* __restrict__ bias, const float* __restrict__ beta,
               float* __restrict__ out) {
    extern __shared__ char smem[];
    int tid = threadIdx.x, wid = tid >> 5, lane = tid & 31;
    int warp_m = wid & 3;          // 0..3 -> M offset 64*warp_m
    int warp_n = wid >> 2;         // 0..1 -> N offset 64*warp_n
    int bm = blockIdx.x >> 4;      // 32 row blocks of 256
    int bn = blockIdx.x & 15;      // 16 col blocks of 128
    const __nv_bfloat16* Ag = g_Aq + (size_t)bm * BM * INF;
    const __nv_bfloat16* Bg = g_Wq + (size_t)bn * BN * INF;

    float acc[4][8][4];
#pragma unroll
    for (int mi = 0; mi < 4; mi++)
#pragma unroll
        for (int ni = 0; ni < 8; ni++)
#pragma unroll
            for (int q = 0; q < 4; q++) acc[mi][ni][q] = 0.f;

    // ldmatrix lane geometry (fixed per thread)
    int lrow = lane & 15;          // row within 16-row group
    int khalf = lane >> 4;         // 0/1 -> +16 B within the k16 step

    // Per-mi A row and per-ni4 B row for this lane
    int arow[4], brow_[4];
#pragma unroll
    for (int mi = 0; mi < 4; mi++) arow[mi] = warp_m * 64 + mi * 16 + lrow;
#pragma unroll
    for (int n4 = 0; n4 < 4; n4++) brow_[n4] = warp_n * 64 + n4 * 16 + lrow;

    // Prologue: stages 0..2
    load_stage(smem, 0, Ag, Bg, 0, tid); CP_COMMIT();
    load_stage(smem, 1, Ag, Bg, 1, tid); CP_COMMIT();
    load_stage(smem, 2, Ag, Bg, 2, tid); CP_COMMIT();

    for (int kt = 0; kt < NT; kt++) {
        CP_WAIT2();
        __syncthreads();
        if (kt + 3 < NT) load_stage(smem, (kt + 3) & 3, Ag, Bg, kt + 3, tid);
        CP_COMMIT();

        uint32_t abase = smem_u32(smem + (kt & 3) * STAGE);
        uint32_t bbase = abase + A_BYTES;

#pragma unroll
        for (int ks = 0; ks < 4; ks++) {   // 4 k16 steps per BK=64 tile
            int chunk = ks * 2 + khalf;
            uint32_t af[4][4], bf[8][2];
#pragma unroll
            for (int mi = 0; mi < 4; mi++)
                ldsm_x4(af[mi], abase + sw_off(arow[mi], chunk));
#pragma unroll
            for (int n4 = 0; n4 < 4; n4++) {
                uint32_t r[4];
                ldsm_x4(r, bbase + sw_off(brow_[n4], chunk));
                bf[n4 * 2 + 0][0] = r[0]; bf[n4 * 2 + 1][0] = r[1];
                bf[n4 * 2 + 0][1] = r[2]; bf[n4 * 2 + 1][1] = r[3];
            }
#pragma unroll
            for (int mi = 0; mi < 4; mi++)
#pragma unroll
                for (int ni = 0; ni < 8; ni++)
                    mma16816(acc[mi][ni], af[mi], bf[ni]);
        }
        __syncthreads();
    }

    // Epilogue
    int g = lane >> 2, t4 = lane & 3;
#pragma unroll
    for (int mi = 0; mi < 4; mi++) {
        int row0 = bm * BM + warp_m * 64 + mi * 16 + g;
        int row1 = row0 + 8;
        float s0 = g_scale[row0], s1 = g_scale[row1];
        float* o0 = out + (size_t)row0 * OUTF;
        float* o1 = out + (size_t)row1 * OUTF;
#pragma unroll
        for (int ni = 0; ni < 8; ni++) {
            int col = bn * BN + warp_n * 64 + ni * 8 + 2 * t4;
            float bi0 = bias[col], bi1 = bias[col + 1];
            float be0 = beta[col], be1 = beta[col + 1];
            float2 v0, v1;
            v0.x = (acc[mi][ni][0] * s0 + bi0) * be0;
            v0.y = (acc[mi][ni][1] * s0 + bi1) * be1;
            v1.x = (acc[mi][ni][2] * s1 + bi0) * be0;
            v1.y = (acc[mi][ni][3] * s1 + bi1) * be1;
            *(float2*)(o0 + col) = v0;
            *(float2*)(o1 + col) = v1;
        }
    }
}

// ---------------------------------------------------------------------------
// Launch
// ---------------------------------------------------------------------------
extern "C" void kernel_launch(void* const* d_in, const int* in_sizes, int n_in,
                              void* d_out, int out_size) {
    const float* input  = (const float*)d_in[0];
    const float* weight = (const float*)d_in[1];
    const float* bias   = (const float*)d_in[2];
    const float* gamma  = (const float*)d_in[3];
    const float* beta   = (const float*)d_in[4];
    float* out = (float*)d_out;

    quant_input_kernel<<<NROWS, 256>>>(input, gamma);
    quant_weight_kernel<<<(OUTF * INF / 4) / 256, 256>>>(weight);

    cudaFuncSetAttribute(bitlinear_gemm,
                         cudaFuncAttributeMaxDynamicSharedMemorySize, SMEM_TOTAL);
    bitlinear_gemm<<<(NROWS / BM) * (OUTF / BN), 256, SMEM_TOTAL>>>(bias, beta, out);
}